// round 3
// baseline (speedup 1.0000x reference)
#include <cuda_runtime.h>

// MultiblockConv: y[b][n] = conv3x3( pad(x_b[n] with x_{1-b}[n] wrap columns, zero rows) , W ) + bias
// b in {0,1}, n in {0,1}. Cin=64, Cout=128, H=W=256.
//
// Round 1 (resubmit of round 0 — infra failure, kernel never ran):
// register-blocked direct FFMA conv.
//  - block tile: 32 (w) x 64 (h) pixels, 8 output channels
//  - thread: 8 pixels (w) x 8 co  -> 64 fp32 accumulators
//  - smem: weights for co-group (8x64x9 = 18 KB, loaded once)
//          input chunk 2 ci x 66 x 34 (pitch 35 -> bank-conflict-free) = 18.5 KB
//  - grid: (8, 4, 4 images * 16 co-groups)

#define HW      256
#define CIN     64
#define COUT    128
#define TILE_W  32
#define TILE_H  64
#define PX      8     // pixels per thread along w
#define NCO     8     // output channels per block/thread
#define CI_CHUNK 2
#define SROWS   (TILE_H + 2)   // 66
#define SCOLS   (TILE_W + 2)   // 34
#define SPITCH  35             // conflict-free pitch for 8-row x 4-colgroup warps
#define IMG_STRIDE (CIN * HW * HW)   // per (n) image within x0/x1
#define CH_STRIDE  (HW * HW)

__global__ __launch_bounds__(256, 2)
void mbconv_kernel(const float* __restrict__ x0,
                   const float* __restrict__ x1,
                   const float* __restrict__ wgt,
                   const float* __restrict__ bias,
                   float* __restrict__ out)
{
    __shared__ float sW[NCO * CIN * 9];                 // [co_l][ci][k]
    __shared__ float sIn[CI_CHUNK][SROWS * SPITCH];

    const int tid = threadIdx.x;
    const int tx  = tid & 3;     // 0..3  (w group: 8 pixels each)
    const int ty  = tid >> 2;    // 0..63 (row within tile)

    const int w0  = blockIdx.x * TILE_W;
    const int h0  = blockIdx.y * TILE_H;
    const int z   = blockIdx.z;
    const int img = z & 3;       // b*2 + n
    const int cog = z >> 2;      // 0..15 (group of 8 output channels)
    const int b   = img >> 1;
    const int n   = img & 1;

    const float* mainp = (b == 0 ? x0 : x1) + (size_t)n * IMG_STRIDE;
    const float* othp  = (b == 0 ? x1 : x0) + (size_t)n * IMG_STRIDE;

    // Load this co-group's weights (contiguous 8*64*9 floats) once.
    for (int i = tid; i < NCO * CIN * 9; i += 256)
        sW[i] = wgt[cog * (NCO * CIN * 9) + i];

    float acc[NCO][PX];
    #pragma unroll
    for (int co = 0; co < NCO; co++)
        #pragma unroll
        for (int j = 0; j < PX; j++)
            acc[co][j] = 0.0f;

    for (int c = 0; c < CIN; c += CI_CHUNK) {
        __syncthreads();   // previous compute done with sIn

        // Load input chunk: CI_CHUNK channels of the (66 x 34) halo tile.
        for (int i = tid; i < CI_CHUNK * SROWS * SCOLS; i += 256) {
            int ci  = i / (SROWS * SCOLS);
            int rem = i - ci * (SROWS * SCOLS);
            int r   = rem / SCOLS;
            int col = rem - r * SCOLS;
            int h   = h0 - 1 + r;
            int w   = w0 - 1 + col;
            float v = 0.0f;
            if (h >= 0 && h < HW) {
                int cb = (c + ci) * CH_STRIDE + h * HW;
                if (w < 0)         v = othp[cb + (HW - 1)];  // left wrap column from other tensor
                else if (w >= HW)  v = othp[cb + 0];          // right wrap column from other tensor
                else               v = mainp[cb + w];
            }
            sIn[ci][r * SPITCH + col] = v;
        }
        __syncthreads();   // also orders sW on the first iteration

        #pragma unroll
        for (int ci = 0; ci < CI_CHUNK; ci++) {
            #pragma unroll
            for (int kh = 0; kh < 3; kh++) {
                const float* srow = &sIn[ci][(ty + kh) * SPITCH + tx * PX];
                float in[PX + 2];
                #pragma unroll
                for (int m = 0; m < PX + 2; m++) in[m] = srow[m];

                #pragma unroll
                for (int co = 0; co < NCO; co++) {
                    const float* wp = &sW[(co * CIN + (c + ci)) * 9 + kh * 3];
                    const float wv0 = wp[0], wv1 = wp[1], wv2 = wp[2];
                    #pragma unroll
                    for (int j = 0; j < PX; j++) {
                        acc[co][j] = fmaf(in[j],     wv0, acc[co][j]);
                        acc[co][j] = fmaf(in[j + 1], wv1, acc[co][j]);
                        acc[co][j] = fmaf(in[j + 2], wv2, acc[co][j]);
                    }
                }
            }
        }
    }

    // Epilogue: add bias, write 8 contiguous floats per co as two float4s.
    const int hh = h0 + ty;
    const int wb = w0 + tx * PX;
    #pragma unroll
    for (int co = 0; co < NCO; co++) {
        const float bv = __ldg(&bias[cog * NCO + co]);
        float* op = out + (size_t)(img * COUT + cog * NCO + co) * CH_STRIDE + hh * HW + wb;
        float4 o0 = make_float4(acc[co][0] + bv, acc[co][1] + bv,
                                acc[co][2] + bv, acc[co][3] + bv);
        float4 o1 = make_float4(acc[co][4] + bv, acc[co][5] + bv,
                                acc[co][6] + bv, acc[co][7] + bv);
        *reinterpret_cast<float4*>(op)     = o0;
        *reinterpret_cast<float4*>(op + 4) = o1;
    }
}

extern "C" void kernel_launch(void* const* d_in, const int* in_sizes, int n_in,
                              void* d_out, int out_size)
{
    const float* x0   = (const float*)d_in[0];
    const float* x1   = (const float*)d_in[1];
    const float* wgt  = (const float*)d_in[2];
    const float* bias = (const float*)d_in[3];
    float* out = (float*)d_out;

    dim3 grid(HW / TILE_W, HW / TILE_H, 4 * (COUT / NCO));  // (8, 4, 64)
    dim3 block(256);
    mbconv_kernel<<<grid, block>>>(x0, x1, wgt, bias, out);
}

// round 4
// speedup vs baseline: 1.0079x; 1.0079x over previous
#include <cuda_runtime.h>

// MultiblockConv: y[b][n] = conv3x3( pad(x_b[n] with x_{1-b}[n] wrap columns, zero rows) , W ) + bias
// b in {0,1}, n in {0,1}. Cin=64, Cout=128, H=W=256.
//
// Round 1 (resubmit of round 0 — infra failure, kernel never ran):
// register-blocked direct FFMA conv.
//  - block tile: 32 (w) x 64 (h) pixels, 8 output channels
//  - thread: 8 pixels (w) x 8 co  -> 64 fp32 accumulators
//  - smem: weights for co-group (8x64x9 = 18 KB, loaded once)
//          input chunk 2 ci x 66 x 34 (pitch 35 -> bank-conflict-free) = 18.5 KB
//  - grid: (8, 4, 4 images * 16 co-groups)

#define HW      256
#define CIN     64
#define COUT    128
#define TILE_W  32
#define TILE_H  64
#define PX      8     // pixels per thread along w
#define NCO     8     // output channels per block/thread
#define CI_CHUNK 2
#define SROWS   (TILE_H + 2)   // 66
#define SCOLS   (TILE_W + 2)   // 34
#define SPITCH  35             // conflict-free pitch for 8-row x 4-colgroup warps
#define IMG_STRIDE (CIN * HW * HW)   // per (n) image within x0/x1
#define CH_STRIDE  (HW * HW)

__global__ __launch_bounds__(256, 2)
void mbconv_kernel(const float* __restrict__ x0,
                   const float* __restrict__ x1,
                   const float* __restrict__ wgt,
                   const float* __restrict__ bias,
                   float* __restrict__ out)
{
    __shared__ float sW[NCO * CIN * 9];                 // [co_l][ci][k]
    __shared__ float sIn[CI_CHUNK][SROWS * SPITCH];

    const int tid = threadIdx.x;
    const int tx  = tid & 3;     // 0..3  (w group: 8 pixels each)
    const int ty  = tid >> 2;    // 0..63 (row within tile)

    const int w0  = blockIdx.x * TILE_W;
    const int h0  = blockIdx.y * TILE_H;
    const int z   = blockIdx.z;
    const int img = z & 3;       // b*2 + n
    const int cog = z >> 2;      // 0..15 (group of 8 output channels)
    const int b   = img >> 1;
    const int n   = img & 1;

    const float* mainp = (b == 0 ? x0 : x1) + (size_t)n * IMG_STRIDE;
    const float* othp  = (b == 0 ? x1 : x0) + (size_t)n * IMG_STRIDE;

    // Load this co-group's weights (contiguous 8*64*9 floats) once.
    for (int i = tid; i < NCO * CIN * 9; i += 256)
        sW[i] = wgt[cog * (NCO * CIN * 9) + i];

    float acc[NCO][PX];
    #pragma unroll
    for (int co = 0; co < NCO; co++)
        #pragma unroll
        for (int j = 0; j < PX; j++)
            acc[co][j] = 0.0f;

    for (int c = 0; c < CIN; c += CI_CHUNK) {
        __syncthreads();   // previous compute done with sIn

        // Load input chunk: CI_CHUNK channels of the (66 x 34) halo tile.
        for (int i = tid; i < CI_CHUNK * SROWS * SCOLS; i += 256) {
            int ci  = i / (SROWS * SCOLS);
            int rem = i - ci * (SROWS * SCOLS);
            int r   = rem / SCOLS;
            int col = rem - r * SCOLS;
            int h   = h0 - 1 + r;
            int w   = w0 - 1 + col;
            float v = 0.0f;
            if (h >= 0 && h < HW) {
                int cb = (c + ci) * CH_STRIDE + h * HW;
                if (w < 0)         v = othp[cb + (HW - 1)];  // left wrap column from other tensor
                else if (w >= HW)  v = othp[cb + 0];          // right wrap column from other tensor
                else               v = mainp[cb + w];
            }
            sIn[ci][r * SPITCH + col] = v;
        }
        __syncthreads();   // also orders sW on the first iteration

        #pragma unroll
        for (int ci = 0; ci < CI_CHUNK; ci++) {
            #pragma unroll
            for (int kh = 0; kh < 3; kh++) {
                const float* srow = &sIn[ci][(ty + kh) * SPITCH + tx * PX];
                float in[PX + 2];
                #pragma unroll
                for (int m = 0; m < PX + 2; m++) in[m] = srow[m];

                #pragma unroll
                for (int co = 0; co < NCO; co++) {
                    const float* wp = &sW[(co * CIN + (c + ci)) * 9 + kh * 3];
                    const float wv0 = wp[0], wv1 = wp[1], wv2 = wp[2];
                    #pragma unroll
                    for (int j = 0; j < PX; j++) {
                        acc[co][j] = fmaf(in[j],     wv0, acc[co][j]);
                        acc[co][j] = fmaf(in[j + 1], wv1, acc[co][j]);
                        acc[co][j] = fmaf(in[j + 2], wv2, acc[co][j]);
                    }
                }
            }
        }
    }

    // Epilogue: add bias, write 8 contiguous floats per co as two float4s.
    const int hh = h0 + ty;
    const int wb = w0 + tx * PX;
    #pragma unroll
    for (int co = 0; co < NCO; co++) {
        const float bv = __ldg(&bias[cog * NCO + co]);
        float* op = out + (size_t)(img * COUT + cog * NCO + co) * CH_STRIDE + hh * HW + wb;
        float4 o0 = make_float4(acc[co][0] + bv, acc[co][1] + bv,
                                acc[co][2] + bv, acc[co][3] + bv);
        float4 o1 = make_float4(acc[co][4] + bv, acc[co][5] + bv,
                                acc[co][6] + bv, acc[co][7] + bv);
        *reinterpret_cast<float4*>(op)     = o0;
        *reinterpret_cast<float4*>(op + 4) = o1;
    }
}

extern "C" void kernel_launch(void* const* d_in, const int* in_sizes, int n_in,
                              void* d_out, int out_size)
{
    const float* x0   = (const float*)d_in[0];
    const float* x1   = (const float*)d_in[1];
    const float* wgt  = (const float*)d_in[2];
    const float* bias = (const float*)d_in[3];
    float* out = (float*)d_out;

    dim3 grid(HW / TILE_W, HW / TILE_H, 4 * (COUT / NCO));  // (8, 4, 64)
    dim3 block(256);
    mbconv_kernel<<<grid, block>>>(x0, x1, wgt, bias, out);
}